// round 10
// baseline (speedup 1.0000x reference)
#include <cuda_runtime.h>
#include <cuda_fp16.h>

// RelTemporalEncoding collapsed (exact by linearity):
//   Y = emb @ W^T + b            (3000x62 one-time precompute, fp32 math)
//   out[n,:] = w0*Y[t0] + w1*Y[t1] + w2*Y[t2]
//
// R10 (= R7/R8/R9 resubmitted; all three prior rounds were GPU-acquisition
// infra timeouts — this kernel has never executed): persistent gather,
// unroll x4 with phase-batched loads (12 t-LDGs, then 12 Y-LDGs in flight)
// to halve dependent-chain exposure vs R6's unroll x2. fp16 Y table
// (128B/row = 1 L1 line per gathered row).
//
// Inputs: t int32 [1e6,3], emb f32 [3000,62], W f32 [62,62], b f32 [62]
// Output: f32 [1e6, 62]

#define N_HID   62
#define MAX_LEN 3000
#define YP      64              // half-pitch: 64 halves = 128B per table row
#define GT      256             // gather threads/block
#define GBLKS   (148 * 8)       // persistent-ish grid
#define UN      4               // rows in flight per thread

__device__ __half g_Yh[MAX_LEN * YP];

// ---------------------------------------------------------------------------
// Kernel 1: Y = emb @ W^T + b -> fp16. 64 threads (one per output col),
// 4 rows per block, W row kept in regs across the 4 FMA chains.
// ---------------------------------------------------------------------------
#define PR 4
__global__ void precompute_Y(const float* __restrict__ emb,
                             const float* __restrict__ W,
                             const float* __restrict__ b) {
    __shared__ float se[PR][N_HID];
    const int r0 = blockIdx.x * PR;
    const int o  = threadIdx.x;          // 0..63

    for (int i = o; i < PR * N_HID; i += 64)
        se[i / N_HID][i % N_HID] = emb[r0 * N_HID + i];
    __syncthreads();

    float acc0 = 0.f, acc1 = 0.f, acc2 = 0.f, acc3 = 0.f;
    if (o < N_HID) {
        const float* wrow = W + o * N_HID;
        float bb = b[o];
        acc0 = bb; acc1 = bb; acc2 = bb; acc3 = bb;
        #pragma unroll
        for (int d = 0; d < N_HID; ++d) {
            const float w = __ldg(&wrow[d]);
            acc0 = fmaf(se[0][d], w, acc0);
            acc1 = fmaf(se[1][d], w, acc1);
            acc2 = fmaf(se[2][d], w, acc2);
            acc3 = fmaf(se[3][d], w, acc3);
        }
    }
    g_Yh[(r0 + 0) * YP + o] = __float2half_rn(acc0);   // o>=62 -> 0
    g_Yh[(r0 + 1) * YP + o] = __float2half_rn(acc1);
    g_Yh[(r0 + 2) * YP + o] = __float2half_rn(acc2);
    g_Yh[(r0 + 3) * YP + o] = __float2half_rn(acc3);
}

// ---------------------------------------------------------------------------
// Compute + store for one gathered row given its three Y float2s.
// ---------------------------------------------------------------------------
__device__ __forceinline__ void finish_row(float2 av, float2 cv, float2 sv,
                                           float* __restrict__ out,
                                           int row, int c) {
    const __half2* ah = (const __half2*)&av;
    const __half2* ch = (const __half2*)&cv;
    const __half2* sh = (const __half2*)&sv;

    const float2 a0 = __half22float2(ah[0]), a1 = __half22float2(ah[1]);
    const float2 c0 = __half22float2(ch[0]), c1 = __half22float2(ch[1]);
    const float2 s0 = __half22float2(sh[0]), s1 = __half22float2(sh[1]);

    const float w0 = 3600.0f / 3661.0f;
    const float w1 = 60.0f   / 3661.0f;
    const float w2 = 1.0f    / 3661.0f;

    float2 r0, r1;
    r0.x = fmaf(a0.x, w0, fmaf(c0.x, w1, s0.x * w2));
    r0.y = fmaf(a0.y, w0, fmaf(c0.y, w1, s0.y * w2));
    r1.x = fmaf(a1.x, w0, fmaf(c1.x, w1, s1.x * w2));
    r1.y = fmaf(a1.y, w0, fmaf(c1.y, w1, s1.y * w2));

    float* o = out + (size_t)row * N_HID + c * 4;
    __stcs((float2*)o, r0);
    if (c < 15)                          // c==15 covers cols 60..61 only
        __stcs((float2*)(o + 2), r1);
}

__device__ __forceinline__ void do_row(const int* __restrict__ t,
                                       const float2* __restrict__ Yh,
                                       float* __restrict__ out,
                                       int row, int c) {
    const int t0 = __ldg(&t[row * 3 + 0]);
    const int t1 = __ldg(&t[row * 3 + 1]);
    const int t2 = __ldg(&t[row * 3 + 2]);
    finish_row(__ldg(&Yh[t0 * 16 + c]),
               __ldg(&Yh[t1 * 16 + c]),
               __ldg(&Yh[t2 * 16 + c]), out, row, c);
}

// ---------------------------------------------------------------------------
// Kernel 2: persistent grid-stride gather, unroll x4, phase-batched loads.
// ---------------------------------------------------------------------------
__global__ __launch_bounds__(GT, 4)
void gather_p(const int* __restrict__ t, float* __restrict__ out, int n_rows) {
    const int g = blockIdx.x * GT + threadIdx.x;
    const int c = g & 15;                       // column group (0..15)
    const int stride = (gridDim.x * GT) >> 4;   // row slots in the grid
    int row = g >> 4;

    const float2* __restrict__ Yh = (const float2*)g_Yh;

    for (; row + (UN - 1) * stride < n_rows; row += UN * stride) {
        int tt[UN][3];
        // Phase 1: all t loads in flight (12 LDGs, DRAM-latency batch)
        #pragma unroll
        for (int i = 0; i < UN; ++i) {
            const int r = row + i * stride;
            tt[i][0] = __ldg(&t[r * 3 + 0]);
            tt[i][1] = __ldg(&t[r * 3 + 1]);
            tt[i][2] = __ldg(&t[r * 3 + 2]);
        }
        // Phase 2: all Y gathers in flight (12 LDG.64)
        float2 av[UN], cv[UN], sv[UN];
        #pragma unroll
        for (int i = 0; i < UN; ++i) {
            av[i] = __ldg(&Yh[tt[i][0] * 16 + c]);
            cv[i] = __ldg(&Yh[tt[i][1] * 16 + c]);
            sv[i] = __ldg(&Yh[tt[i][2] * 16 + c]);
        }
        // Phase 3: compute + store
        #pragma unroll
        for (int i = 0; i < UN; ++i)
            finish_row(av[i], cv[i], sv[i], out, row + i * stride, c);
    }
    // tail
    for (; row < n_rows; row += stride)
        do_row(t, Yh, out, row, c);
}

// ---------------------------------------------------------------------------
extern "C" void kernel_launch(void* const* d_in, const int* in_sizes, int n_in,
                              void* d_out, int out_size) {
    const int*   t   = (const int*)  d_in[0];
    const float* emb = (const float*)d_in[1];
    const float* W   = (const float*)d_in[2];
    const float* b   = (const float*)d_in[3];
    float* out = (float*)d_out;

    precompute_Y<<<MAX_LEN / PR, 64>>>(emb, W, b);    // 750 blocks

    const int n_rows = out_size / N_HID;              // 1,000,000
    gather_p<<<GBLKS, GT>>>(t, out, n_rows);
}

// round 14
// speedup vs baseline: 1.1223x; 1.1223x over previous
#include <cuda_runtime.h>
#include <cuda_fp16.h>

// RelTemporalEncoding collapsed (exact by linearity):
//   Y = emb @ W^T + b            (3000x62 one-time precompute, fp32 math)
//   out[n,:] = w0*Y[t0] + w1*Y[t1] + w2*Y[t2]
//
// R14 (= R11/R12/R13 resubmitted; all prior rounds were GPU-acquisition
// infra timeouts — this kernel has never executed): warp-centric ROW-PAIR
// gather targeting the l1tex wavefront ceiling (R10: L1 67.8% = top pipe;
// in-flight-load capacity proven non-binding).
//  - t: one LDG (6 contiguous ints per pair) + 3 SHFL broadcasts  (3->0.6 wf/row)
//  - stores: shfl-realigned full-density STG.128 over the 496B pair
//    region (16B-aligned since 496=31*16)                         (4->2 wf/row)
//  - Y gathers unchanged (1 line per gathered row, 3/row minimal)
//  - UN=2 pairs in flight; fp16 Y table (128B/row = 1 line)
//
// Inputs: t int32 [1e6,3], emb f32 [3000,62], W f32 [62,62], b f32 [62]
// Output: f32 [1e6, 62]

#define N_HID   62
#define MAX_LEN 3000
#define YP      64              // half-pitch: 64 halves = 128B per table row
#define GT      256
#define GBLKS   (148 * 8)
#define FULLM   0xFFFFFFFFu

__device__ __half g_Yh[MAX_LEN * YP];

// ---------------------------------------------------------------------------
// Kernel 1: Y = emb @ W^T + b -> fp16 (unchanged from R6/R10).
// ---------------------------------------------------------------------------
#define PR 4
__global__ void precompute_Y(const float* __restrict__ emb,
                             const float* __restrict__ W,
                             const float* __restrict__ b) {
    __shared__ float se[PR][N_HID];
    const int r0 = blockIdx.x * PR;
    const int o  = threadIdx.x;          // 0..63

    for (int i = o; i < PR * N_HID; i += 64)
        se[i / N_HID][i % N_HID] = emb[r0 * N_HID + i];
    __syncthreads();

    float acc0 = 0.f, acc1 = 0.f, acc2 = 0.f, acc3 = 0.f;
    if (o < N_HID) {
        const float* wrow = W + o * N_HID;
        float bb = b[o];
        acc0 = bb; acc1 = bb; acc2 = bb; acc3 = bb;
        #pragma unroll
        for (int d = 0; d < N_HID; ++d) {
            const float w = __ldg(&wrow[d]);
            acc0 = fmaf(se[0][d], w, acc0);
            acc1 = fmaf(se[1][d], w, acc1);
            acc2 = fmaf(se[2][d], w, acc2);
            acc3 = fmaf(se[3][d], w, acc3);
        }
    }
    g_Yh[(r0 + 0) * YP + o] = __float2half_rn(acc0);   // o>=62 -> 0
    g_Yh[(r0 + 1) * YP + o] = __float2half_rn(acc1);
    g_Yh[(r0 + 2) * YP + o] = __float2half_rn(acc2);
    g_Yh[(r0 + 3) * YP + o] = __float2half_rn(acc3);
}

// ---------------------------------------------------------------------------
// Per-pair compute: given this lane's three Y float2s (4 halves each),
// produce the lane's float4 (its row's cols 4c..4c+3; lane c==15 has
// garbage in .z/.w which is never stored).
// ---------------------------------------------------------------------------
__device__ __forceinline__ float4 lerp4(float2 av, float2 cv, float2 sv) {
    const __half2* ah = (const __half2*)&av;
    const __half2* ch = (const __half2*)&cv;
    const __half2* sh = (const __half2*)&sv;

    const float2 a0 = __half22float2(ah[0]), a1 = __half22float2(ah[1]);
    const float2 c0 = __half22float2(ch[0]), c1 = __half22float2(ch[1]);
    const float2 s0 = __half22float2(sh[0]), s1 = __half22float2(sh[1]);

    const float w0 = 3600.0f / 3661.0f;
    const float w1 = 60.0f   / 3661.0f;
    const float w2 = 1.0f    / 3661.0f;

    float4 r;
    r.x = fmaf(a0.x, w0, fmaf(c0.x, w1, s0.x * w2));
    r.y = fmaf(a0.y, w0, fmaf(c0.y, w1, s0.y * w2));
    r.z = fmaf(a1.x, w0, fmaf(c1.x, w1, s1.x * w2));
    r.w = fmaf(a1.y, w0, fmaf(c1.y, w1, s1.y * w2));
    return r;
}

// Shuffle-realign + store one pair's 496B region as 31 aligned float4s.
__device__ __forceinline__ void store_pair(float4 r, float4* __restrict__ out4,
                                           long long p, int lane) {
    const float nx = __shfl_down_sync(FULLM, r.x, 1);
    const float ny = __shfl_down_sync(FULLM, r.y, 1);

    float4 s;
    if (lane < 15)       s = r;                              // rowA cols 4l..4l+3
    else if (lane == 15) s = make_float4(r.x, r.y, nx, ny);  // A:60,61 | B:0,1
    else                 s = make_float4(r.z, r.w, nx, ny);  // B: 4c+2..4c+5
    if (lane < 31)
        __stcs(&out4[p * 31 + lane], s);
}

// ---------------------------------------------------------------------------
// Kernel 2: persistent warp-per-row-pair gather, 2 pairs in flight.
// ---------------------------------------------------------------------------
__global__ __launch_bounds__(GT)
void gather_pair(const int* __restrict__ t, float4* __restrict__ out4,
                 int n_pairs) {
    const int lane   = threadIdx.x & 31;
    const int warp_g = (blockIdx.x * GT + threadIdx.x) >> 5;
    const int nwarps = (GBLKS * GT) >> 5;          // 9472

    const int tb = (lane >= 16) ? 3 : 0;           // triplet base within pair
    const int c  = lane & 15;                      // column group

    const float2* __restrict__ Yh = (const float2*)g_Yh;

    int p = warp_g;
    for (; p + nwarps < n_pairs; p += 2 * nwarps) {
        const int p1 = p + nwarps;

        // Phase 1: t loads (lanes 0..5 load the pair's 6 contiguous ints)
        int tv0 = 0, tv1 = 0;
        if (lane < 6) {
            tv0 = __ldg(&t[6 * p  + lane]);
            tv1 = __ldg(&t[6 * p1 + lane]);
        }
        const int a0 = __shfl_sync(FULLM, tv0, tb + 0);
        const int a1 = __shfl_sync(FULLM, tv0, tb + 1);
        const int a2 = __shfl_sync(FULLM, tv0, tb + 2);
        const int b0 = __shfl_sync(FULLM, tv1, tb + 0);
        const int b1 = __shfl_sync(FULLM, tv1, tb + 1);
        const int b2 = __shfl_sync(FULLM, tv1, tb + 2);

        // Phase 2: all Y gathers in flight (6 LDG.64 per lane)
        const float2 av0 = __ldg(&Yh[a0 * 16 + c]);
        const float2 cv0 = __ldg(&Yh[a1 * 16 + c]);
        const float2 sv0 = __ldg(&Yh[a2 * 16 + c]);
        const float2 av1 = __ldg(&Yh[b0 * 16 + c]);
        const float2 cv1 = __ldg(&Yh[b1 * 16 + c]);
        const float2 sv1 = __ldg(&Yh[b2 * 16 + c]);

        // Phase 3: compute + shuffled aligned stores
        store_pair(lerp4(av0, cv0, sv0), out4, p,  lane);
        store_pair(lerp4(av1, cv1, sv1), out4, p1, lane);
    }
    for (; p < n_pairs; p += nwarps) {
        int tv = 0;
        if (lane < 6) tv = __ldg(&t[6 * p + lane]);
        const int q0 = __shfl_sync(FULLM, tv, tb + 0);
        const int q1 = __shfl_sync(FULLM, tv, tb + 1);
        const int q2 = __shfl_sync(FULLM, tv, tb + 2);
        store_pair(lerp4(__ldg(&Yh[q0 * 16 + c]),
                         __ldg(&Yh[q1 * 16 + c]),
                         __ldg(&Yh[q2 * 16 + c])), out4, p, lane);
    }
}

// Fallback for an odd final row (not hit for n_rows = 1e6; kept for safety).
__global__ void gather_last_row(const int* __restrict__ t,
                                float* __restrict__ out, int row) {
    const int c = threadIdx.x;                  // 0..15
    const int t0 = t[row * 3 + 0], t1 = t[row * 3 + 1], t2 = t[row * 3 + 2];
    const float2* Yh = (const float2*)g_Yh;
    float4 r = lerp4(__ldg(&Yh[t0 * 16 + c]),
                     __ldg(&Yh[t1 * 16 + c]),
                     __ldg(&Yh[t2 * 16 + c]));
    float* o = out + (size_t)row * N_HID + c * 4;
    o[0] = r.x; o[1] = r.y;
    if (c < 15) { o[2] = r.z; o[3] = r.w; }
}

// ---------------------------------------------------------------------------
extern "C" void kernel_launch(void* const* d_in, const int* in_sizes, int n_in,
                              void* d_out, int out_size) {
    const int*   t   = (const int*)  d_in[0];
    const float* emb = (const float*)d_in[1];
    const float* W   = (const float*)d_in[2];
    const float* b   = (const float*)d_in[3];

    precompute_Y<<<MAX_LEN / PR, 64>>>(emb, W, b);    // 750 blocks

    const int n_rows  = out_size / N_HID;             // 1,000,000
    const int n_pairs = n_rows / 2;                   // 500,000
    gather_pair<<<GBLKS, GT>>>(t, (float4*)d_out, n_pairs);
    if (n_rows & 1)
        gather_last_row<<<1, 16>>>(t, (float*)d_out, n_rows - 1);
}